// round 15
// baseline (speedup 1.0000x reference)
#include <cuda_runtime.h>
#include <cuda_fp16.h>
#include <math.h>

#define NE    30      // electrons
#define NA    10      // atoms
#define NN    40      // en-graph nodes
#define FEAT  64
#define NPE   435     // ee unique pairs
#define NPN   300     // en unique pairs
#define NL    2
#define T_TAB 2048
#define INV_STEP 128.0f   // T_TAB / 16.0 range
#define BLK   512
#define NWARP (BLK / 32)

typedef unsigned long long u64;

// paired fp16 tables: [i][f2] = { half2(row i), half2(row i+1) }
__device__ uint2 g_tab_ee[T_TAB * 32];
__device__ uint2 g_tab_en[T_TAB * 32];

// ---- packed f32x2 helpers (Blackwell) -------------------------------------
__device__ __forceinline__ u64 pack2(float x, float y) {
    u64 r; asm("mov.b64 %0, {%1,%2};" : "=l"(r) : "f"(x), "f"(y)); return r;
}
__device__ __forceinline__ float2 unpack2(u64 v) {
    float2 f; asm("mov.b64 {%0,%1}, %2;" : "=f"(f.x), "=f"(f.y) : "l"(v)); return f;
}
#define FMA2(d, a, b, c) asm("fma.rn.f32x2 %0, %1, %2, %3;" : "=l"(d) : "l"(a), "l"(b), "l"(c))
#define ADD2(d, a, b)    asm("add.rn.f32x2 %0, %1, %2;"     : "=l"(d) : "l"(a), "l"(b))

// clamp-free tanh: exact limits at +-inf
__device__ __forceinline__ float tanh_fast(float x) {
    float e = __expf(2.f * x);
    return 1.f - __fdividef(2.f, e + 1.f);
}

// ---------------------------------------------------------------------------
// Table build: grid (T_TAB/32, 2), block 256. Emits paired half2 rows.
// ---------------------------------------------------------------------------
__global__ void build_tab_kernel(const float* __restrict__ wf_ee,
                                 const float* __restrict__ bf_ee,
                                 const float* __restrict__ wf_en,
                                 const float* __restrict__ bf_en) {
    __shared__ float s_wf[FEAT * FEAT];
    __shared__ float s_rbf[32][FEAT];
    const float* wf = blockIdx.y ? wf_en : wf_ee;
    const float* bf = blockIdx.y ? bf_en : bf_ee;
    uint2* tab      = blockIdx.y ? g_tab_en : g_tab_ee;
    unsigned* tabw  = (unsigned*)tab;

    const int t = threadIdx.x;
    for (int i = t; i < FEAT * FEAT; i += 256) s_wf[i] = wf[i];

    const int f  = t & 63;
    const int rg = t >> 6;
    const int base = blockIdx.x * 32;

    #pragma unroll
    for (int rr = 0; rr < 8; rr++) {
        int r = rg + rr * 4;
        float d = (float)(base + r) * (1.0f / INV_STEP);
        float x = d - (float)f * (8.0f / 63.0f);
        s_rbf[r][f] = __expf(-x * x);
    }
    __syncthreads();

    float bfv = bf[f];
    float a[8];
    #pragma unroll
    for (int rr = 0; rr < 8; rr++) a[rr] = bfv;
    #pragma unroll
    for (int k = 0; k < FEAT; k++) {
        float w = s_wf[k * FEAT + f];
        #pragma unroll
        for (int rr = 0; rr < 8; rr++)
            a[rr] = fmaf(s_rbf[rg + rr * 4][k], w, a[rr]);
    }
    #pragma unroll
    for (int rr = 0; rr < 8; rr++) {
        int r = base + rg + rr * 4;
        float v  = tanhf(a[rr]);
        float vh = __shfl_down_sync(0xffffffffu, v, 1);
        if ((f & 1) == 0) {
            __half2 h2 = __floats2half2_rn(v, vh);
            unsigned bits = *(unsigned*)&h2;
            int f2 = f >> 1;
            tabw[(r * 32 + f2) * 2 + 0] = bits;
            if (r > 0) tabw[((r - 1) * 32 + f2) * 2 + 1] = bits;
        }
    }
}

// ---------------------------------------------------------------------------
struct __align__(16) Smem {
    __half2 filt2[NPE * 32];      // 55,680 B; en uses first 300*32, emb_en
                                  // aliased at byte offset 38,400 in en section
    float   h[NN * FEAT];         // 10,240
    float   agg[NN * FEAT];       // 10,240 (also ee distance scratch)
    float4  wlT[NL * 32 * 32];    // 32,768
    float   bl[NL * FEAT];        // 512
    float   wr[FEAT];             // 256
    float   embee[2 * FEAT];      // 512
    float   xyz[NE * 3];          // 360
    float   atm[NA * 3];          // 120
    float   den[NPN];             // 1,200 (en distances, overlap-computed)
    float   red[NWARP];           // 64  (ee readout partials)
    float   red2[NWARP];          // 64  (en readout partials)
};                                 // ~112,016 B -> 2 CTAs/SM

__device__ __forceinline__ void stage_weights(Smem& S, const float* wl,
                                              const float* bl, const float* wr, int t) {
    for (int idx = t; idx < NL * 32 * 32; idx += BLK) {
        int l = idx >> 10, r = idx & 1023;
        int kk = r >> 5, fp = r & 31;
        const float* s0 = &wl[(l * FEAT + 2 * kk) * FEAT + 2 * fp];
        float4 v;
        v.x = s0[0]; v.y = s0[1];
        v.z = s0[FEAT]; v.w = s0[FEAT + 1];
        S.wlT[idx] = v;
    }
    for (int i = t; i < NL * FEAT; i += BLK) S.bl[i] = bl[i];
    if (t < FEAT) S.wr[t] = wr[t];
}

// core: compute tanh-args (agg @ wl + bl) for up to 4 nodes into ca[4].
__device__ __forceinline__ void linear4_core(Smem& S, int l, int node0, int nlim,
                                             int fp, u64 ca[4]) {
    u64 bias = *(const u64*)&S.bl[l * FEAT + 2 * fp];
    u64 cb[4];
    #pragma unroll
    for (int s = 0; s < 4; s++) { ca[s] = bias; cb[s] = 0; }
    const float4* wT = &S.wlT[l * 1024 + fp];
    #pragma unroll
    for (int kk = 0; kk < 32; kk += 2) {
        float4 w0 = wT[kk * 32];
        float4 w1 = wT[(kk + 1) * 32];
        u64 w0a = pack2(w0.x, w0.y), w0b = pack2(w0.z, w0.w);
        u64 w1a = pack2(w1.x, w1.y), w1b = pack2(w1.z, w1.w);
        #pragma unroll
        for (int s = 0; s < 4; s++) {
            int n = node0 + s;
            if (n < nlim) {
                float4 av = *(const float4*)&S.agg[n * FEAT + 2 * kk];  // broadcast
                u64 d;
                d = pack2(av.x, av.x); FMA2(ca[s], d, w0a, ca[s]);
                d = pack2(av.y, av.y); FMA2(cb[s], d, w0b, cb[s]);
                d = pack2(av.z, av.z); FMA2(ca[s], d, w1a, ca[s]);
                d = pack2(av.w, av.w); FMA2(cb[s], d, w1b, cb[s]);
            }
        }
    }
    #pragma unroll
    for (int s = 0; s < 4; s++) ADD2(ca[s], ca[s], cb[s]);
}

// layer-0 linear: h[n] = emb_row(n) + tanh(core); writes h.
template <bool EE>
__device__ __forceinline__ void linear4_l0(Smem& S, const float* embsrc,
                                           int node0, int nlim, int fp) {
    u64 ca[4];
    linear4_core(S, 0, node0, nlim, fp, ca);
    #pragma unroll
    for (int s = 0; s < 4; s++) {
        int n = node0 + s;
        if (n < nlim) {
            int ty = EE ? (n < 15 ? 0 : 1)
                        : (n < 15 ? 0 : (n < NE ? 1 : 2 + (n - NE)));
            float2 ev = *(const float2*)&embsrc[ty * FEAT + 2 * fp];
            float2 sv = unpack2(ca[s]);
            ev.x += tanh_fast(sv.x);
            ev.y += tanh_fast(sv.y);
            *(float2*)&S.h[n * FEAT + 2 * fp] = ev;
        }
    }
}

// last-layer linear with readout fold: r += (h_prev + tanh(core)) . wr
__device__ __forceinline__ void linear4_fold(Smem& S, float* red, int warp,
                                             int node0, int nlim, int fp) {
    u64 ca[4];
    linear4_core(S, NL - 1, node0, nlim, fp, ca);
    float2 w = *(const float2*)&S.wr[2 * fp];
    float r = 0.f;
    #pragma unroll
    for (int s = 0; s < 4; s++) {
        int n = node0 + s;
        if (n < nlim) {
            float2 sv = unpack2(ca[s]);
            float2 hv = *(const float2*)&S.h[n * FEAT + 2 * fp];
            r += (hv.x + tanh_fast(sv.x)) * w.x + (hv.y + tanh_fast(sv.y)) * w.y;
        }
    }
    #pragma unroll
    for (int o = 16; o; o >>= 1) r += __shfl_down_sync(0xffffffffu, r, o);
    if ((threadIdx.x & 31) == 0) red[warp] = r;
}

__global__ void __launch_bounds__(BLK, 2) jastrow_kernel(
    const float* __restrict__ pos,    const float* __restrict__ atoms,
    const float* __restrict__ emb_ee, const float* __restrict__ wl_ee,
    const float* __restrict__ bl_ee,  const float* __restrict__ wr_ee,
    const float* __restrict__ br_ee,
    const float* __restrict__ emb_en, const float* __restrict__ wl_en,
    const float* __restrict__ bl_en,  const float* __restrict__ wr_en,
    const float* __restrict__ br_en,
    float* __restrict__ out) {
    extern __shared__ char smem_raw[];
    Smem& S = *reinterpret_cast<Smem*>(smem_raw);
    float* Sd = S.agg;   // ee distance scratch (dead once filt2_ee is built)
    float* embeen = (float*)((char*)S.filt2 + NPN * 32 * sizeof(__half2)); // filt2 tail
    const int t = threadIdx.x;
    const int b = blockIdx.x;
    const int warp = t >> 5;
    const int fp = t & 31;

    for (int i = t; i < NE * 3; i += BLK) S.xyz[i] = pos[b * NE * 3 + i];
    for (int i = t; i < NA * 3; i += BLK) S.atm[i] = atoms[i];
    if (t < 2 * FEAT) S.embee[t] = emb_ee[t];
    stage_weights(S, wl_ee, bl_ee, wr_ee, t);
    __syncthreads();

    // ================= EE graph =================
    for (int x = t; x < NE * NE; x += BLK) {
        int i = x / NE, j = x % NE;
        if (i < j) {
            int p = ((i * (2 * NE - 1 - i)) >> 1) + j - i - 1;
            float dx = S.xyz[i * 3 + 0] - S.xyz[j * 3 + 0];
            float dy = S.xyz[i * 3 + 1] - S.xyz[j * 3 + 1];
            float dz = S.xyz[i * 3 + 2] - S.xyz[j * 3 + 2];
            Sd[p] = sqrtf(dx * dx + dy * dy + dz * dz);
        }
    }
    __syncthreads();

    #pragma unroll 2
    for (int it = t; it < NPE * 32; it += BLK) {
        int p = it >> 5, f2 = it & 31;
        float u = fminf(Sd[p] * INV_STEP, (float)(T_TAB - 2) + 0.999f);
        int idx = (int)u;
        float w = u - (float)idx;
        uint2 vv = g_tab_ee[idx * 32 + f2];
        __half2 v0 = *(__half2*)&vv.x, v1 = *(__half2*)&vv.y;
        __half2 wh = __float2half2_rn(w);
        S.filt2[it] = __hfma2(wh, __hsub2(v1, v0), v0);
    }
    __syncthreads();

    // ---- layer 0: factored gather (warps 0-14); warp 15: en distances ----
    if (warp < 15) {
        const int n0 = 2 * warp, n1 = n0 + 1;
        const int Bn0 = ((n0 * (2 * NE - 1 - n0)) >> 1) - n0 - 1;
        const int Bn1 = ((n1 * (2 * NE - 1 - n1)) >> 1) - n1 - 1;
        u64 su0 = 0, sd0 = 0, su1 = 0, sd1 = 0;
        #pragma unroll
        for (int j = 0; j < NE; j++) {
            const int K1 = ((j * (2 * NE - 1 - j)) >> 1) - j - 1;
            if (j != n0) {
                int p = (j < n0) ? (K1 + n0) : (Bn0 + j);
                float2 fv = __half22float2(S.filt2[p * 32 + fp]);
                u64 f2 = pack2(fv.x, fv.y);
                if (j < 15) { ADD2(su0, su0, f2); } else { ADD2(sd0, sd0, f2); }
            }
            if (j != n1) {
                int p = (j < n1) ? (K1 + n1) : (Bn1 + j);
                float2 fv = __half22float2(S.filt2[p * 32 + fp]);
                u64 f2 = pack2(fv.x, fv.y);
                if (j < 15) { ADD2(su1, su1, f2); } else { ADD2(sd1, sd1, f2); }
            }
        }
        u64 e0 = *(const u64*)&S.embee[2 * fp];
        u64 e1 = *(const u64*)&S.embee[FEAT + 2 * fp];
        u64 a0, a1, z = 0;
        FMA2(a0, su0, e0, z); FMA2(a0, sd0, e1, a0);
        FMA2(a1, su1, e0, z); FMA2(a1, sd1, e1, a1);
        *(u64*)&S.agg[n0 * FEAT + 2 * fp] = a0;
        *(u64*)&S.agg[n1 * FEAT + 2 * fp] = a1;
    } else {
        // warp 15: compute en distances (atom-major q = a*NE + e)
        for (int q = fp; q < NPN; q += 32) {
            int a = q / NE, e = q - a * NE;
            float dx = S.xyz[e * 3 + 0] - S.atm[a * 3 + 0];
            float dy = S.xyz[e * 3 + 1] - S.atm[a * 3 + 1];
            float dz = S.xyz[e * 3 + 2] - S.atm[a * 3 + 2];
            S.den[q] = sqrtf(dx * dx + dy * dy + dz * dz);
        }
    }
    __syncthreads();
    if (warp < 8) linear4_l0<true>(S, S.embee, 4 * warp, NE, fp);
    __syncthreads();

    // ---- layer 1: full gather ----
    if (warp < 15) {
        const int n0 = 2 * warp, n1 = n0 + 1;
        const int Bn0 = ((n0 * (2 * NE - 1 - n0)) >> 1) - n0 - 1;
        const int Bn1 = ((n1 * (2 * NE - 1 - n1)) >> 1) - n1 - 1;
        u64 a0a = 0, a0b = 0, a1a = 0, a1b = 0;
        #pragma unroll
        for (int j = 0; j < NE; j++) {
            const int K1 = ((j * (2 * NE - 1 - j)) >> 1) - j - 1;
            u64 hv = *(const u64*)&S.h[j * FEAT + 2 * fp];
            if (j != n0) {
                int p = (j < n0) ? (K1 + n0) : (Bn0 + j);
                float2 fv = __half22float2(S.filt2[p * 32 + fp]);
                u64 f2 = pack2(fv.x, fv.y);
                if (j & 1) { FMA2(a0b, hv, f2, a0b); } else { FMA2(a0a, hv, f2, a0a); }
            }
            if (j != n1) {
                int p = (j < n1) ? (K1 + n1) : (Bn1 + j);
                float2 fv = __half22float2(S.filt2[p * 32 + fp]);
                u64 f2 = pack2(fv.x, fv.y);
                if (j & 1) { FMA2(a1b, hv, f2, a1b); } else { FMA2(a1a, hv, f2, a1a); }
            }
        }
        ADD2(a0a, a0a, a0b);
        ADD2(a1a, a1a, a1b);
        *(u64*)&S.agg[n0 * FEAT + 2 * fp] = a0a;
        *(u64*)&S.agg[n1 * FEAT + 2 * fp] = a1a;
    }
    __syncthreads();

    // ---- overlap: ee fold (warps 0-7) || en filt build (warps 8-15) ----
    // filt2_ee is dead (L1 gather done); den was written 2 barriers ago.
    if (warp < 8) {
        linear4_fold(S, S.red, warp, 4 * warp, NE, fp);
    } else {
        for (int it = t - 256; it < NPN * 32; it += 256) {
            int q = it >> 5, f2 = it & 31;
            float u = fminf(S.den[q] * INV_STEP, (float)(T_TAB - 2) + 0.999f);
            int idx = (int)u;
            float w = u - (float)idx;
            uint2 vv = g_tab_en[idx * 32 + f2];
            __half2 v0 = *(__half2*)&vv.x, v1 = *(__half2*)&vv.y;
            __half2 wh = __float2half2_rn(w);
            S.filt2[it] = __hfma2(wh, __hsub2(v1, v0), v0);
        }
    }
    __syncthreads();

    // ================= EN graph =================
    stage_weights(S, wl_en, bl_en, wr_en, t);
    for (int i = t; i < (2 + NA) * FEAT; i += BLK) embeen[i] = emb_en[i];
    __syncthreads();

    // ---- layer 0: gather (warps 0-5: 5 electrons; warps 6-15: 1 atom) ----
    if (warp < 6) {
        const int base = 5 * warp;
        u64 acc[5] = {0, 0, 0, 0, 0};
        #pragma unroll
        for (int aa = 0; aa < NA; aa++) {
            u64 hv = *(const u64*)&embeen[(2 + aa) * FEAT + 2 * fp];
            #pragma unroll
            for (int s = 0; s < 5; s++) {
                float2 fv = __half22float2(S.filt2[(aa * NE + base + s) * 32 + fp]);
                u64 f2 = pack2(fv.x, fv.y);
                FMA2(acc[s], hv, f2, acc[s]);
            }
        }
        #pragma unroll
        for (int s = 0; s < 5; s++)
            *(u64*)&S.agg[(base + s) * FEAT + 2 * fp] = acc[s];
    } else {
        const int a = warp - 6;           // atom node: factored over e-types
        u64 su = 0, sd = 0;
        #pragma unroll
        for (int e = 0; e < NE; e++) {
            float2 fv = __half22float2(S.filt2[(a * NE + e) * 32 + fp]);
            u64 f2 = pack2(fv.x, fv.y);
            if (e < 15) { ADD2(su, su, f2); } else { ADD2(sd, sd, f2); }
        }
        u64 e0 = *(const u64*)&embeen[2 * fp];
        u64 e1 = *(const u64*)&embeen[FEAT + 2 * fp];
        u64 c, z = 0;
        FMA2(c, su, e0, z); FMA2(c, sd, e1, c);
        *(u64*)&S.agg[(NE + a) * FEAT + 2 * fp] = c;
    }
    __syncthreads();
    if (warp < 10) linear4_l0<false>(S, embeen, 4 * warp, NN, fp);
    __syncthreads();

    // ---- layer 1: full gather + fold ----
    if (warp < 6) {
        const int base = 5 * warp;
        u64 acc[5] = {0, 0, 0, 0, 0};
        #pragma unroll
        for (int aa = 0; aa < NA; aa++) {
            u64 hv = *(const u64*)&S.h[(NE + aa) * FEAT + 2 * fp];
            #pragma unroll
            for (int s = 0; s < 5; s++) {
                float2 fv = __half22float2(S.filt2[(aa * NE + base + s) * 32 + fp]);
                u64 f2 = pack2(fv.x, fv.y);
                FMA2(acc[s], hv, f2, acc[s]);
            }
        }
        #pragma unroll
        for (int s = 0; s < 5; s++)
            *(u64*)&S.agg[(base + s) * FEAT + 2 * fp] = acc[s];
    } else {
        const int a = warp - 6;
        u64 ca = 0, cb = 0;
        #pragma unroll
        for (int e = 0; e < NE; e++) {
            u64 hv = *(const u64*)&S.h[e * FEAT + 2 * fp];
            float2 fv = __half22float2(S.filt2[(a * NE + e) * 32 + fp]);
            u64 f2 = pack2(fv.x, fv.y);
            if (e & 1) { FMA2(cb, hv, f2, cb); } else { FMA2(ca, hv, f2, ca); }
        }
        ADD2(ca, ca, cb);
        *(u64*)&S.agg[(NE + a) * FEAT + 2 * fp] = ca;
    }
    __syncthreads();
    if (warp < 10) linear4_fold(S, S.red2, warp, 4 * warp, NN, fp);
    __syncthreads();

    if (t == 0) {
        float kee = br_ee[0], ken = br_en[0];
        #pragma unroll
        for (int w = 0; w < 8; w++) kee += S.red[w];
        #pragma unroll
        for (int w = 0; w < 10; w++) ken += S.red2[w];
        out[b] = expf(kee + ken);
    }
}

// ---------------------------------------------------------------------------
extern "C" void kernel_launch(void* const* d_in, const int* in_sizes, int n_in,
                              void* d_out, int out_size) {
    const float* pos    = (const float*)d_in[0];
    const float* atoms  = (const float*)d_in[1];
    const float* emb_ee = (const float*)d_in[2];
    const float* wf_ee  = (const float*)d_in[3];
    const float* bf_ee  = (const float*)d_in[4];
    const float* wl_ee  = (const float*)d_in[5];
    const float* bl_ee  = (const float*)d_in[6];
    const float* wr_ee  = (const float*)d_in[7];
    const float* br_ee  = (const float*)d_in[8];
    const float* emb_en = (const float*)d_in[9];
    const float* wf_en  = (const float*)d_in[10];
    const float* bf_en  = (const float*)d_in[11];
    const float* wl_en  = (const float*)d_in[12];
    const float* bl_en  = (const float*)d_in[13];
    const float* wr_en  = (const float*)d_in[14];
    const float* br_en  = (const float*)d_in[15];
    float* out = (float*)d_out;

    int nb = in_sizes[0] / (NE * 3);

    cudaFuncSetAttribute(jastrow_kernel,
                         cudaFuncAttributeMaxDynamicSharedMemorySize,
                         (int)sizeof(Smem));

    build_tab_kernel<<<dim3(T_TAB / 32, 2), 256>>>(wf_ee, bf_ee, wf_en, bf_en);
    jastrow_kernel<<<nb, BLK, sizeof(Smem)>>>(
        pos, atoms, emb_ee, wl_ee, bl_ee, wr_ee, br_ee,
        emb_en, wl_en, bl_en, wr_en, br_en, out);
}

// round 16
// speedup vs baseline: 1.0037x; 1.0037x over previous
#include <cuda_runtime.h>
#include <cuda_fp16.h>
#include <math.h>

#define NE    30      // electrons
#define NA    10      // atoms
#define NN    40      // en-graph nodes
#define FEAT  64
#define NPE   435     // ee unique pairs
#define NPN   300     // en unique pairs
#define NL    2
#define T_TAB 2048
#define INV_STEP 128.0f   // T_TAB / 16.0 range
#define BLK   512
#define NWARP (BLK / 32)

typedef unsigned long long u64;

// paired fp16 tables: [i][f2] = { half2(row i), half2(row i+1) }
__device__ uint2 g_tab_ee[T_TAB * 32];
__device__ uint2 g_tab_en[T_TAB * 32];

// ---- packed f32x2 helpers (Blackwell) -------------------------------------
__device__ __forceinline__ u64 pack2(float x, float y) {
    u64 r; asm("mov.b64 %0, {%1,%2};" : "=l"(r) : "f"(x), "f"(y)); return r;
}
__device__ __forceinline__ float2 unpack2(u64 v) {
    float2 f; asm("mov.b64 {%0,%1}, %2;" : "=f"(f.x), "=f"(f.y) : "l"(v)); return f;
}
#define FMA2(d, a, b, c) asm("fma.rn.f32x2 %0, %1, %2, %3;" : "=l"(d) : "l"(a), "l"(b), "l"(c))
#define ADD2(d, a, b)    asm("add.rn.f32x2 %0, %1, %2;"     : "=l"(d) : "l"(a), "l"(b))

// clamp-free tanh: exact limits at +-inf
__device__ __forceinline__ float tanh_fast(float x) {
    float e = __expf(2.f * x);
    return 1.f - __fdividef(2.f, e + 1.f);
}

// ---------------------------------------------------------------------------
// Table build: grid (T_TAB/32, 2), block 256. Emits paired half2 rows.
// ---------------------------------------------------------------------------
__global__ void build_tab_kernel(const float* __restrict__ wf_ee,
                                 const float* __restrict__ bf_ee,
                                 const float* __restrict__ wf_en,
                                 const float* __restrict__ bf_en) {
    __shared__ float s_wf[FEAT * FEAT];
    __shared__ float s_rbf[32][FEAT];
    const float* wf = blockIdx.y ? wf_en : wf_ee;
    const float* bf = blockIdx.y ? bf_en : bf_ee;
    uint2* tab      = blockIdx.y ? g_tab_en : g_tab_ee;
    unsigned* tabw  = (unsigned*)tab;

    const int t = threadIdx.x;
    for (int i = t; i < FEAT * FEAT; i += 256) s_wf[i] = wf[i];

    const int f  = t & 63;
    const int rg = t >> 6;
    const int base = blockIdx.x * 32;

    #pragma unroll
    for (int rr = 0; rr < 8; rr++) {
        int r = rg + rr * 4;
        float d = (float)(base + r) * (1.0f / INV_STEP);
        float x = d - (float)f * (8.0f / 63.0f);
        s_rbf[r][f] = __expf(-x * x);
    }
    __syncthreads();

    float bfv = bf[f];
    float a[8];
    #pragma unroll
    for (int rr = 0; rr < 8; rr++) a[rr] = bfv;
    #pragma unroll
    for (int k = 0; k < FEAT; k++) {
        float w = s_wf[k * FEAT + f];
        #pragma unroll
        for (int rr = 0; rr < 8; rr++)
            a[rr] = fmaf(s_rbf[rg + rr * 4][k], w, a[rr]);
    }
    #pragma unroll
    for (int rr = 0; rr < 8; rr++) {
        int r = base + rg + rr * 4;
        float v  = tanhf(a[rr]);
        float vh = __shfl_down_sync(0xffffffffu, v, 1);
        if ((f & 1) == 0) {
            __half2 h2 = __floats2half2_rn(v, vh);
            unsigned bits = *(unsigned*)&h2;
            int f2 = f >> 1;
            // owner of row r fills tab[r].x and tab[r-1].y (disjoint 4B words)
            tabw[(r * 32 + f2) * 2 + 0] = bits;
            if (r > 0) tabw[((r - 1) * 32 + f2) * 2 + 1] = bits;
        }
    }
}

// ---------------------------------------------------------------------------
struct __align__(16) Smem {
    __half2 filt2[NPE * 32];      // 55,680 B; en uses first 300*32, emb_en
                                  // aliased at byte offset 38,400 in en section
    float   h[NN * FEAT];         // 10,240
    float   agg[NN * FEAT];       // 10,240 (also distance scratch)
    float4  wlT[NL * 32 * 32];    // 32,768
    float   bl[NL * FEAT];        // 512
    float   wr[FEAT];             // 256
    float   embee[2 * FEAT];      // 512
    float   xyz[NE * 3];          // 360
    float   atm[NA * 3];          // 120
    float   red[NWARP];           // 64  (ee readout partials)
    float   red2[NWARP];          // 64  (en readout partials)
};                                 // ~110,816 B -> 2 CTAs/SM

__device__ __forceinline__ void stage_weights(Smem& S, const float* wl,
                                              const float* bl, const float* wr, int t) {
    for (int idx = t; idx < NL * 32 * 32; idx += BLK) {
        int l = idx >> 10, r = idx & 1023;
        int kk = r >> 5, fp = r & 31;
        const float* s0 = &wl[(l * FEAT + 2 * kk) * FEAT + 2 * fp];
        float4 v;
        v.x = s0[0]; v.y = s0[1];
        v.z = s0[FEAT]; v.w = s0[FEAT + 1];
        S.wlT[idx] = v;
    }
    for (int i = t; i < NL * FEAT; i += BLK) S.bl[i] = bl[i];
    if (t < FEAT) S.wr[t] = wr[t];
}

// core: compute tanh-args (agg @ wl + bl) for up to 4 nodes into ca[4].
// r9 form: LDS.128-heavy, FMA2 with broadcast packs (MIO-optimal).
__device__ __forceinline__ void linear4_core(Smem& S, int l, int node0, int nlim,
                                             int fp, u64 ca[4]) {
    u64 bias = *(const u64*)&S.bl[l * FEAT + 2 * fp];
    u64 cb[4];
    #pragma unroll
    for (int s = 0; s < 4; s++) { ca[s] = bias; cb[s] = 0; }
    const float4* wT = &S.wlT[l * 1024 + fp];
    #pragma unroll
    for (int kk = 0; kk < 32; kk += 2) {
        float4 w0 = wT[kk * 32];
        float4 w1 = wT[(kk + 1) * 32];
        u64 w0a = pack2(w0.x, w0.y), w0b = pack2(w0.z, w0.w);
        u64 w1a = pack2(w1.x, w1.y), w1b = pack2(w1.z, w1.w);
        #pragma unroll
        for (int s = 0; s < 4; s++) {
            int n = node0 + s;
            if (n < nlim) {
                float4 av = *(const float4*)&S.agg[n * FEAT + 2 * kk];  // broadcast
                u64 d;
                d = pack2(av.x, av.x); FMA2(ca[s], d, w0a, ca[s]);
                d = pack2(av.y, av.y); FMA2(cb[s], d, w0b, cb[s]);
                d = pack2(av.z, av.z); FMA2(ca[s], d, w1a, ca[s]);
                d = pack2(av.w, av.w); FMA2(cb[s], d, w1b, cb[s]);
            }
        }
    }
    #pragma unroll
    for (int s = 0; s < 4; s++) ADD2(ca[s], ca[s], cb[s]);
}

// layer-0 linear: h[n] = emb_row(n) + tanh(core); writes h.
template <bool EE>
__device__ __forceinline__ void linear4_l0(Smem& S, const float* embsrc,
                                           int node0, int nlim, int fp) {
    u64 ca[4];
    linear4_core(S, 0, node0, nlim, fp, ca);
    #pragma unroll
    for (int s = 0; s < 4; s++) {
        int n = node0 + s;
        if (n < nlim) {
            int ty = EE ? (n < 15 ? 0 : 1)
                        : (n < 15 ? 0 : (n < NE ? 1 : 2 + (n - NE)));
            float2 ev = *(const float2*)&embsrc[ty * FEAT + 2 * fp];
            float2 sv = unpack2(ca[s]);
            ev.x += tanh_fast(sv.x);
            ev.y += tanh_fast(sv.y);
            *(float2*)&S.h[n * FEAT + 2 * fp] = ev;
        }
    }
}

// last-layer linear with readout fold: r += (h_prev + tanh(core)) . wr
__device__ __forceinline__ void linear4_fold(Smem& S, float* red, int warp,
                                             int node0, int nlim, int fp) {
    u64 ca[4];
    linear4_core(S, NL - 1, node0, nlim, fp, ca);
    float2 w = *(const float2*)&S.wr[2 * fp];
    float r = 0.f;
    #pragma unroll
    for (int s = 0; s < 4; s++) {
        int n = node0 + s;
        if (n < nlim) {
            float2 sv = unpack2(ca[s]);
            float2 hv = *(const float2*)&S.h[n * FEAT + 2 * fp];
            r += (hv.x + tanh_fast(sv.x)) * w.x + (hv.y + tanh_fast(sv.y)) * w.y;
        }
    }
    #pragma unroll
    for (int o = 16; o; o >>= 1) r += __shfl_down_sync(0xffffffffu, r, o);
    if ((threadIdx.x & 31) == 0) red[warp] = r;
}

__global__ void __launch_bounds__(BLK, 2) jastrow_kernel(
    const float* __restrict__ pos,    const float* __restrict__ atoms,
    const float* __restrict__ emb_ee, const float* __restrict__ wl_ee,
    const float* __restrict__ bl_ee,  const float* __restrict__ wr_ee,
    const float* __restrict__ br_ee,
    const float* __restrict__ emb_en, const float* __restrict__ wl_en,
    const float* __restrict__ bl_en,  const float* __restrict__ wr_en,
    const float* __restrict__ br_en,
    float* __restrict__ out) {
    extern __shared__ char smem_raw[];
    Smem& S = *reinterpret_cast<Smem*>(smem_raw);
    float* Sd = S.agg;   // distance scratch (dead once filt2 is built)
    float* embeen = (float*)((char*)S.filt2 + NPN * 32 * sizeof(__half2)); // filt2 tail
    const int t = threadIdx.x;
    const int b = blockIdx.x;
    const int warp = t >> 5;
    const int fp = t & 31;

    for (int i = t; i < NE * 3; i += BLK) S.xyz[i] = pos[b * NE * 3 + i];
    for (int i = t; i < NA * 3; i += BLK) S.atm[i] = atoms[i];
    if (t < 2 * FEAT) S.embee[t] = emb_ee[t];
    stage_weights(S, wl_ee, bl_ee, wr_ee, t);
    __syncthreads();

    // ================= EE graph =================
    for (int x = t; x < NE * NE; x += BLK) {
        int i = x / NE, j = x % NE;
        if (i < j) {
            int p = ((i * (2 * NE - 1 - i)) >> 1) + j - i - 1;
            float dx = S.xyz[i * 3 + 0] - S.xyz[j * 3 + 0];
            float dy = S.xyz[i * 3 + 1] - S.xyz[j * 3 + 1];
            float dz = S.xyz[i * 3 + 2] - S.xyz[j * 3 + 2];
            Sd[p] = sqrtf(dx * dx + dy * dy + dz * dz);
        }
    }
    __syncthreads();

    #pragma unroll 2
    for (int it = t; it < NPE * 32; it += BLK) {
        int p = it >> 5, f2 = it & 31;
        float u = fminf(Sd[p] * INV_STEP, (float)(T_TAB - 2) + 0.999f);
        int idx = (int)u;
        float w = u - (float)idx;
        uint2 vv = g_tab_ee[idx * 32 + f2];
        __half2 v0 = *(__half2*)&vv.x, v1 = *(__half2*)&vv.y;
        __half2 wh = __float2half2_rn(w);
        S.filt2[it] = __hfma2(wh, __hsub2(v1, v0), v0);
    }
    __syncthreads();

    // ---- layer 0: factored gather (h0 = emb[type]) ----
    if (warp < 15) {
        const int n0 = 2 * warp, n1 = n0 + 1;
        const int Bn0 = ((n0 * (2 * NE - 1 - n0)) >> 1) - n0 - 1;
        const int Bn1 = ((n1 * (2 * NE - 1 - n1)) >> 1) - n1 - 1;
        u64 su0 = 0, sd0 = 0, su1 = 0, sd1 = 0;
        #pragma unroll
        for (int j = 0; j < NE; j++) {
            const int K1 = ((j * (2 * NE - 1 - j)) >> 1) - j - 1;
            if (j != n0) {
                int p = (j < n0) ? (K1 + n0) : (Bn0 + j);
                float2 fv = __half22float2(S.filt2[p * 32 + fp]);
                u64 f2 = pack2(fv.x, fv.y);
                if (j < 15) { ADD2(su0, su0, f2); } else { ADD2(sd0, sd0, f2); }
            }
            if (j != n1) {
                int p = (j < n1) ? (K1 + n1) : (Bn1 + j);
                float2 fv = __half22float2(S.filt2[p * 32 + fp]);
                u64 f2 = pack2(fv.x, fv.y);
                if (j < 15) { ADD2(su1, su1, f2); } else { ADD2(sd1, sd1, f2); }
            }
        }
        u64 e0 = *(const u64*)&S.embee[2 * fp];
        u64 e1 = *(const u64*)&S.embee[FEAT + 2 * fp];
        u64 a0, a1, z = 0;
        FMA2(a0, su0, e0, z); FMA2(a0, sd0, e1, a0);
        FMA2(a1, su1, e0, z); FMA2(a1, sd1, e1, a1);
        *(u64*)&S.agg[n0 * FEAT + 2 * fp] = a0;
        *(u64*)&S.agg[n1 * FEAT + 2 * fp] = a1;
    }
    __syncthreads();
    if (warp < 8) linear4_l0<true>(S, S.embee, 4 * warp, NE, fp);
    __syncthreads();

    // ---- layer 1: full gather + fold ----
    if (warp < 15) {
        const int n0 = 2 * warp, n1 = n0 + 1;
        const int Bn0 = ((n0 * (2 * NE - 1 - n0)) >> 1) - n0 - 1;
        const int Bn1 = ((n1 * (2 * NE - 1 - n1)) >> 1) - n1 - 1;
        u64 a0a = 0, a0b = 0, a1a = 0, a1b = 0;
        #pragma unroll
        for (int j = 0; j < NE; j++) {
            const int K1 = ((j * (2 * NE - 1 - j)) >> 1) - j - 1;
            u64 hv = *(const u64*)&S.h[j * FEAT + 2 * fp];
            if (j != n0) {
                int p = (j < n0) ? (K1 + n0) : (Bn0 + j);
                float2 fv = __half22float2(S.filt2[p * 32 + fp]);
                u64 f2 = pack2(fv.x, fv.y);
                if (j & 1) { FMA2(a0b, hv, f2, a0b); } else { FMA2(a0a, hv, f2, a0a); }
            }
            if (j != n1) {
                int p = (j < n1) ? (K1 + n1) : (Bn1 + j);
                float2 fv = __half22float2(S.filt2[p * 32 + fp]);
                u64 f2 = pack2(fv.x, fv.y);
                if (j & 1) { FMA2(a1b, hv, f2, a1b); } else { FMA2(a1a, hv, f2, a1a); }
            }
        }
        ADD2(a0a, a0a, a0b);
        ADD2(a1a, a1a, a1b);
        *(u64*)&S.agg[n0 * FEAT + 2 * fp] = a0a;
        *(u64*)&S.agg[n1 * FEAT + 2 * fp] = a1a;
    }
    __syncthreads();
    if (warp < 8) linear4_fold(S, S.red, warp, 4 * warp, NE, fp);
    __syncthreads();

    // ================= EN graph =================
    for (int q = t; q < NPN; q += BLK) {
        int a = q / NE, e = q % NE;
        float dx = S.xyz[e * 3 + 0] - S.atm[a * 3 + 0];
        float dy = S.xyz[e * 3 + 1] - S.atm[a * 3 + 1];
        float dz = S.xyz[e * 3 + 2] - S.atm[a * 3 + 2];
        Sd[q] = sqrtf(dx * dx + dy * dy + dz * dz);
    }
    stage_weights(S, wl_en, bl_en, wr_en, t);
    for (int i = t; i < (2 + NA) * FEAT; i += BLK) embeen[i] = emb_en[i];
    __syncthreads();

    #pragma unroll 2
    for (int it = t; it < NPN * 32; it += BLK) {
        int q = it >> 5, f2 = it & 31;
        float u = fminf(Sd[q] * INV_STEP, (float)(T_TAB - 2) + 0.999f);
        int idx = (int)u;
        float w = u - (float)idx;
        uint2 vv = g_tab_en[idx * 32 + f2];
        __half2 v0 = *(__half2*)&vv.x, v1 = *(__half2*)&vv.y;
        __half2 wh = __float2half2_rn(w);
        S.filt2[it] = __hfma2(wh, __hsub2(v1, v0), v0);
    }
    __syncthreads();

    // ---- layer 0: gather (warps 0-5: 5 electrons; warps 6-15: 1 atom) ----
    if (warp < 6) {
        const int base = 5 * warp;
        u64 acc[5] = {0, 0, 0, 0, 0};
        #pragma unroll
        for (int aa = 0; aa < NA; aa++) {
            u64 hv = *(const u64*)&embeen[(2 + aa) * FEAT + 2 * fp];
            #pragma unroll
            for (int s = 0; s < 5; s++) {
                float2 fv = __half22float2(S.filt2[(aa * NE + base + s) * 32 + fp]);
                u64 f2 = pack2(fv.x, fv.y);
                FMA2(acc[s], hv, f2, acc[s]);
            }
        }
        #pragma unroll
        for (int s = 0; s < 5; s++)
            *(u64*)&S.agg[(base + s) * FEAT + 2 * fp] = acc[s];
    } else {
        const int a = warp - 6;           // atom node: factored over e-types
        u64 su = 0, sd = 0;
        #pragma unroll
        for (int e = 0; e < NE; e++) {
            float2 fv = __half22float2(S.filt2[(a * NE + e) * 32 + fp]);
            u64 f2 = pack2(fv.x, fv.y);
            if (e < 15) { ADD2(su, su, f2); } else { ADD2(sd, sd, f2); }
        }
        u64 e0 = *(const u64*)&embeen[2 * fp];
        u64 e1 = *(const u64*)&embeen[FEAT + 2 * fp];
        u64 c, z = 0;
        FMA2(c, su, e0, z); FMA2(c, sd, e1, c);
        *(u64*)&S.agg[(NE + a) * FEAT + 2 * fp] = c;
    }
    __syncthreads();
    if (warp < 10) linear4_l0<false>(S, embeen, 4 * warp, NN, fp);
    __syncthreads();

    // ---- layer 1: full gather + fold ----
    if (warp < 6) {
        const int base = 5 * warp;
        u64 acc[5] = {0, 0, 0, 0, 0};
        #pragma unroll
        for (int aa = 0; aa < NA; aa++) {
            u64 hv = *(const u64*)&S.h[(NE + aa) * FEAT + 2 * fp];
            #pragma unroll
            for (int s = 0; s < 5; s++) {
                float2 fv = __half22float2(S.filt2[(aa * NE + base + s) * 32 + fp]);
                u64 f2 = pack2(fv.x, fv.y);
                FMA2(acc[s], hv, f2, acc[s]);
            }
        }
        #pragma unroll
        for (int s = 0; s < 5; s++)
            *(u64*)&S.agg[(base + s) * FEAT + 2 * fp] = acc[s];
    } else {
        const int a = warp - 6;
        u64 ca = 0, cb = 0;
        #pragma unroll
        for (int e = 0; e < NE; e++) {
            u64 hv = *(const u64*)&S.h[e * FEAT + 2 * fp];
            float2 fv = __half22float2(S.filt2[(a * NE + e) * 32 + fp]);
            u64 f2 = pack2(fv.x, fv.y);
            if (e & 1) { FMA2(cb, hv, f2, cb); } else { FMA2(ca, hv, f2, ca); }
        }
        ADD2(ca, ca, cb);
        *(u64*)&S.agg[(NE + a) * FEAT + 2 * fp] = ca;
    }
    __syncthreads();
    if (warp < 10) linear4_fold(S, S.red2, warp, 4 * warp, NN, fp);
    __syncthreads();

    if (t == 0) {
        float kee = br_ee[0], ken = br_en[0];
        #pragma unroll
        for (int w = 0; w < 8; w++) kee += S.red[w];
        #pragma unroll
        for (int w = 0; w < 10; w++) ken += S.red2[w];
        out[b] = expf(kee + ken);
    }
}

// ---------------------------------------------------------------------------
extern "C" void kernel_launch(void* const* d_in, const int* in_sizes, int n_in,
                              void* d_out, int out_size) {
    const float* pos    = (const float*)d_in[0];
    const float* atoms  = (const float*)d_in[1];
    const float* emb_ee = (const float*)d_in[2];
    const float* wf_ee  = (const float*)d_in[3];
    const float* bf_ee  = (const float*)d_in[4];
    const float* wl_ee  = (const float*)d_in[5];
    const float* bl_ee  = (const float*)d_in[6];
    const float* wr_ee  = (const float*)d_in[7];
    const float* br_ee  = (const float*)d_in[8];
    const float* emb_en = (const float*)d_in[9];
    const float* wf_en  = (const float*)d_in[10];
    const float* bf_en  = (const float*)d_in[11];
    const float* wl_en  = (const float*)d_in[12];
    const float* bl_en  = (const float*)d_in[13];
    const float* wr_en  = (const float*)d_in[14];
    const float* br_en  = (const float*)d_in[15];
    float* out = (float*)d_out;

    int nb = in_sizes[0] / (NE * 3);

    cudaFuncSetAttribute(jastrow_kernel,
                         cudaFuncAttributeMaxDynamicSharedMemorySize,
                         (int)sizeof(Smem));

    build_tab_kernel<<<dim3(T_TAB / 32, 2), 256>>>(wf_ee, bf_ee, wf_en, bf_en);
    jastrow_kernel<<<nb, BLK, sizeof(Smem)>>>(
        pos, atoms, emb_ee, wl_ee, bl_ee, wr_ee, br_ee,
        emb_en, wl_en, bl_en, wr_en, br_en, out);
}

// round 17
// speedup vs baseline: 1.0891x; 1.0851x over previous
#include <cuda_runtime.h>
#include <cuda_fp16.h>
#include <math.h>

#define NE    30      // electrons
#define NA    10      // atoms
#define NN    40      // en-graph nodes
#define FEAT  64
#define NPE   435     // ee unique pairs
#define NPN   300     // en unique pairs
#define NL    2
#define T_TAB 2048
#define INV_STEP 128.0f   // T_TAB / 16.0 range
#define BLK   512
#define NWARP (BLK / 32)

typedef unsigned long long u64;

// paired fp16 tables: [i][f2] = { half2(row i), half2(row i+1) }
__device__ uint2 g_tab_ee[T_TAB * 32];
__device__ uint2 g_tab_en[T_TAB * 32];

// ---- packed f32x2 helpers (Blackwell) -------------------------------------
__device__ __forceinline__ u64 pack2(float x, float y) {
    u64 r; asm("mov.b64 %0, {%1,%2};" : "=l"(r) : "f"(x), "f"(y)); return r;
}
__device__ __forceinline__ float2 unpack2(u64 v) {
    float2 f; asm("mov.b64 {%0,%1}, %2;" : "=f"(f.x), "=f"(f.y) : "l"(v)); return f;
}
#define FMA2(d, a, b, c) asm("fma.rn.f32x2 %0, %1, %2, %3;" : "=l"(d) : "l"(a), "l"(b), "l"(c))
#define ADD2(d, a, b)    asm("add.rn.f32x2 %0, %1, %2;"     : "=l"(d) : "l"(a), "l"(b))

// clamp-free tanh: exact limits at +-inf
__device__ __forceinline__ float tanh_fast(float x) {
    float e = __expf(2.f * x);
    return 1.f - __fdividef(2.f, e + 1.f);
}

// ---------------------------------------------------------------------------
// Table build: grid (T_TAB/32, 2), block 256. Emits paired half2 rows.
// ---------------------------------------------------------------------------
__global__ void build_tab_kernel(const float* __restrict__ wf_ee,
                                 const float* __restrict__ bf_ee,
                                 const float* __restrict__ wf_en,
                                 const float* __restrict__ bf_en) {
    __shared__ float s_wf[FEAT * FEAT];
    __shared__ float s_rbf[32][FEAT];
    const float* wf = blockIdx.y ? wf_en : wf_ee;
    const float* bf = blockIdx.y ? bf_en : bf_ee;
    uint2* tab      = blockIdx.y ? g_tab_en : g_tab_ee;
    unsigned* tabw  = (unsigned*)tab;

    const int t = threadIdx.x;
    for (int i = t; i < FEAT * FEAT; i += 256) s_wf[i] = wf[i];

    const int f  = t & 63;
    const int rg = t >> 6;
    const int base = blockIdx.x * 32;

    #pragma unroll
    for (int rr = 0; rr < 8; rr++) {
        int r = rg + rr * 4;
        float d = (float)(base + r) * (1.0f / INV_STEP);
        float x = d - (float)f * (8.0f / 63.0f);
        s_rbf[r][f] = __expf(-x * x);
    }
    __syncthreads();

    float bfv = bf[f];
    float a[8];
    #pragma unroll
    for (int rr = 0; rr < 8; rr++) a[rr] = bfv;
    #pragma unroll
    for (int k = 0; k < FEAT; k++) {
        float w = s_wf[k * FEAT + f];
        #pragma unroll
        for (int rr = 0; rr < 8; rr++)
            a[rr] = fmaf(s_rbf[rg + rr * 4][k], w, a[rr]);
    }
    #pragma unroll
    for (int rr = 0; rr < 8; rr++) {
        int r = base + rg + rr * 4;
        float v  = tanhf(a[rr]);
        float vh = __shfl_down_sync(0xffffffffu, v, 1);
        if ((f & 1) == 0) {
            __half2 h2 = __floats2half2_rn(v, vh);
            unsigned bits = *(unsigned*)&h2;
            int f2 = f >> 1;
            tabw[(r * 32 + f2) * 2 + 0] = bits;
            if (r > 0) tabw[((r - 1) * 32 + f2) * 2 + 1] = bits;
        }
    }
}

// ---------------------------------------------------------------------------
struct __align__(16) Smem {
    __half2 filt2[NPE * 32];      // 55,680 B; en uses first 300*32, emb_en
                                  // aliased at byte offset 38,400 in en section
    float   h[NN * FEAT];         // 10,240
    float   agg[NN * FEAT];       // 10,240 (also distance scratch)
    float4  wlT[NL * 32 * 32];    // 32,768
    float   bl[NL * FEAT];        // 512
    float   wr[FEAT];             // 256
    float   embee[2 * FEAT];      // 512
    float   xyz[2 * NE * 3];      // 720 (both elements)
    float   atm[NA * 3];          // 120
    float   kee[2];               // 8
    float   red[NWARP];           // 64
};                                 // ~111,200 B -> 2 CTAs/SM

__device__ __forceinline__ void stage_weights(Smem& S, const float* wl,
                                              const float* bl, const float* wr, int t) {
    for (int idx = t; idx < NL * 32 * 32; idx += BLK) {
        int l = idx >> 10, r = idx & 1023;
        int kk = r >> 5, fp = r & 31;
        const float* s0 = &wl[(l * FEAT + 2 * kk) * FEAT + 2 * fp];
        float4 v;
        v.x = s0[0]; v.y = s0[1];
        v.z = s0[FEAT]; v.w = s0[FEAT + 1];
        S.wlT[idx] = v;
    }
    for (int i = t; i < NL * FEAT; i += BLK) S.bl[i] = bl[i];
    if (t < FEAT) S.wr[t] = wr[t];
}

// core: compute tanh-args (agg @ wl + bl) for up to 4 nodes into ca[4].
__device__ __forceinline__ void linear4_core(Smem& S, int l, int node0, int nlim,
                                             int fp, u64 ca[4]) {
    u64 bias = *(const u64*)&S.bl[l * FEAT + 2 * fp];
    u64 cb[4];
    #pragma unroll
    for (int s = 0; s < 4; s++) { ca[s] = bias; cb[s] = 0; }
    const float4* wT = &S.wlT[l * 1024 + fp];
    #pragma unroll
    for (int kk = 0; kk < 32; kk += 2) {
        float4 w0 = wT[kk * 32];
        float4 w1 = wT[(kk + 1) * 32];
        u64 w0a = pack2(w0.x, w0.y), w0b = pack2(w0.z, w0.w);
        u64 w1a = pack2(w1.x, w1.y), w1b = pack2(w1.z, w1.w);
        #pragma unroll
        for (int s = 0; s < 4; s++) {
            int n = node0 + s;
            if (n < nlim) {
                float4 av = *(const float4*)&S.agg[n * FEAT + 2 * kk];  // broadcast
                u64 d;
                d = pack2(av.x, av.x); FMA2(ca[s], d, w0a, ca[s]);
                d = pack2(av.y, av.y); FMA2(cb[s], d, w0b, cb[s]);
                d = pack2(av.z, av.z); FMA2(ca[s], d, w1a, ca[s]);
                d = pack2(av.w, av.w); FMA2(cb[s], d, w1b, cb[s]);
            }
        }
    }
    #pragma unroll
    for (int s = 0; s < 4; s++) ADD2(ca[s], ca[s], cb[s]);
}

// layer-0 linear: h[n] = emb_row(n) + tanh(core); writes h.
template <bool EE>
__device__ __forceinline__ void linear4_l0(Smem& S, const float* embsrc,
                                           int node0, int nlim, int fp) {
    u64 ca[4];
    linear4_core(S, 0, node0, nlim, fp, ca);
    #pragma unroll
    for (int s = 0; s < 4; s++) {
        int n = node0 + s;
        if (n < nlim) {
            int ty = EE ? (n < 15 ? 0 : 1)
                        : (n < 15 ? 0 : (n < NE ? 1 : 2 + (n - NE)));
            float2 ev = *(const float2*)&embsrc[ty * FEAT + 2 * fp];
            float2 sv = unpack2(ca[s]);
            ev.x += tanh_fast(sv.x);
            ev.y += tanh_fast(sv.y);
            *(float2*)&S.h[n * FEAT + 2 * fp] = ev;
        }
    }
}

// last-layer linear with readout fold: r += (h_prev + tanh(core)) . wr
__device__ __forceinline__ void linear4_fold(Smem& S, float* red, int warp,
                                             int node0, int nlim, int fp) {
    u64 ca[4];
    linear4_core(S, NL - 1, node0, nlim, fp, ca);
    float2 w = *(const float2*)&S.wr[2 * fp];
    float r = 0.f;
    #pragma unroll
    for (int s = 0; s < 4; s++) {
        int n = node0 + s;
        if (n < nlim) {
            float2 sv = unpack2(ca[s]);
            float2 hv = *(const float2*)&S.h[n * FEAT + 2 * fp];
            r += (hv.x + tanh_fast(sv.x)) * w.x + (hv.y + tanh_fast(sv.y)) * w.y;
        }
    }
    #pragma unroll
    for (int o = 16; o; o >>= 1) r += __shfl_down_sync(0xffffffffu, r, o);
    if ((threadIdx.x & 31) == 0) red[warp] = r;
}

__global__ void __launch_bounds__(BLK, 2) jastrow_kernel(
    const float* __restrict__ pos,    const float* __restrict__ atoms,
    const float* __restrict__ emb_ee, const float* __restrict__ wl_ee,
    const float* __restrict__ bl_ee,  const float* __restrict__ wr_ee,
    const float* __restrict__ br_ee,
    const float* __restrict__ emb_en, const float* __restrict__ wl_en,
    const float* __restrict__ bl_en,  const float* __restrict__ wr_en,
    const float* __restrict__ br_en,
    float* __restrict__ out, int nb) {
    extern __shared__ char smem_raw[];
    Smem& S = *reinterpret_cast<Smem*>(smem_raw);
    float* Sd = S.agg;   // distance scratch (dead once filt2 is built)
    float* embeen = (float*)((char*)S.filt2 + NPN * 32 * sizeof(__half2)); // filt2 tail
    const int t = threadIdx.x;
    const int b0 = blockIdx.x * 2;
    const int warp = t >> 5;
    const int fp = t & 31;

    // load both elements' positions + shared constants, stage ee weights once
    for (int i = t; i < 2 * NE * 3; i += BLK) {
        int e = i / (NE * 3), r = i % (NE * 3);
        int b = b0 + e;
        S.xyz[i] = (b < nb) ? pos[b * NE * 3 + r] : 0.f;
    }
    for (int i = t; i < NA * 3; i += BLK) S.atm[i] = atoms[i];
    if (t < 2 * FEAT) S.embee[t] = emb_ee[t];
    stage_weights(S, wl_ee, bl_ee, wr_ee, t);
    __syncthreads();

    // ================= EE graph: both elements =================
    for (int e = 0; e < 2; e++) {
        if (b0 + e >= nb) break;
        const float* xyz = &S.xyz[e * NE * 3];

        for (int x = t; x < NE * NE; x += BLK) {
            int i = x / NE, j = x % NE;
            if (i < j) {
                int p = ((i * (2 * NE - 1 - i)) >> 1) + j - i - 1;
                float dx = xyz[i * 3 + 0] - xyz[j * 3 + 0];
                float dy = xyz[i * 3 + 1] - xyz[j * 3 + 1];
                float dz = xyz[i * 3 + 2] - xyz[j * 3 + 2];
                Sd[p] = sqrtf(dx * dx + dy * dy + dz * dz);
            }
        }
        __syncthreads();

        #pragma unroll 2
        for (int it = t; it < NPE * 32; it += BLK) {
            int p = it >> 5, f2 = it & 31;
            float u = fminf(Sd[p] * INV_STEP, (float)(T_TAB - 2) + 0.999f);
            int idx = (int)u;
            float w = u - (float)idx;
            uint2 vv = g_tab_ee[idx * 32 + f2];
            __half2 v0 = *(__half2*)&vv.x, v1 = *(__half2*)&vv.y;
            __half2 wh = __float2half2_rn(w);
            S.filt2[it] = __hfma2(wh, __hsub2(v1, v0), v0);
        }
        __syncthreads();

        // layer 0: factored gather (h0 = emb[type])
        if (warp < 15) {
            const int n0 = 2 * warp, n1 = n0 + 1;
            const int Bn0 = ((n0 * (2 * NE - 1 - n0)) >> 1) - n0 - 1;
            const int Bn1 = ((n1 * (2 * NE - 1 - n1)) >> 1) - n1 - 1;
            u64 su0 = 0, sd0 = 0, su1 = 0, sd1 = 0;
            #pragma unroll
            for (int j = 0; j < NE; j++) {
                const int K1 = ((j * (2 * NE - 1 - j)) >> 1) - j - 1;
                if (j != n0) {
                    int p = (j < n0) ? (K1 + n0) : (Bn0 + j);
                    float2 fv = __half22float2(S.filt2[p * 32 + fp]);
                    u64 f2 = pack2(fv.x, fv.y);
                    if (j < 15) { ADD2(su0, su0, f2); } else { ADD2(sd0, sd0, f2); }
                }
                if (j != n1) {
                    int p = (j < n1) ? (K1 + n1) : (Bn1 + j);
                    float2 fv = __half22float2(S.filt2[p * 32 + fp]);
                    u64 f2 = pack2(fv.x, fv.y);
                    if (j < 15) { ADD2(su1, su1, f2); } else { ADD2(sd1, sd1, f2); }
                }
            }
            u64 e0 = *(const u64*)&S.embee[2 * fp];
            u64 e1 = *(const u64*)&S.embee[FEAT + 2 * fp];
            u64 a0, a1, z = 0;
            FMA2(a0, su0, e0, z); FMA2(a0, sd0, e1, a0);
            FMA2(a1, su1, e0, z); FMA2(a1, sd1, e1, a1);
            *(u64*)&S.agg[n0 * FEAT + 2 * fp] = a0;
            *(u64*)&S.agg[n1 * FEAT + 2 * fp] = a1;
        }
        __syncthreads();
        if (warp < 8) linear4_l0<true>(S, S.embee, 4 * warp, NE, fp);
        __syncthreads();

        // layer 1: full gather + fold
        if (warp < 15) {
            const int n0 = 2 * warp, n1 = n0 + 1;
            const int Bn0 = ((n0 * (2 * NE - 1 - n0)) >> 1) - n0 - 1;
            const int Bn1 = ((n1 * (2 * NE - 1 - n1)) >> 1) - n1 - 1;
            u64 a0a = 0, a0b = 0, a1a = 0, a1b = 0;
            #pragma unroll
            for (int j = 0; j < NE; j++) {
                const int K1 = ((j * (2 * NE - 1 - j)) >> 1) - j - 1;
                u64 hv = *(const u64*)&S.h[j * FEAT + 2 * fp];
                if (j != n0) {
                    int p = (j < n0) ? (K1 + n0) : (Bn0 + j);
                    float2 fv = __half22float2(S.filt2[p * 32 + fp]);
                    u64 f2 = pack2(fv.x, fv.y);
                    if (j & 1) { FMA2(a0b, hv, f2, a0b); } else { FMA2(a0a, hv, f2, a0a); }
                }
                if (j != n1) {
                    int p = (j < n1) ? (K1 + n1) : (Bn1 + j);
                    float2 fv = __half22float2(S.filt2[p * 32 + fp]);
                    u64 f2 = pack2(fv.x, fv.y);
                    if (j & 1) { FMA2(a1b, hv, f2, a1b); } else { FMA2(a1a, hv, f2, a1a); }
                }
            }
            ADD2(a0a, a0a, a0b);
            ADD2(a1a, a1a, a1b);
            *(u64*)&S.agg[n0 * FEAT + 2 * fp] = a0a;
            *(u64*)&S.agg[n1 * FEAT + 2 * fp] = a1a;
        }
        __syncthreads();
        if (warp < 8) linear4_fold(S, S.red, warp, 4 * warp, NE, fp);
        __syncthreads();
        if (t == 0) {
            float k = br_ee[0];
            #pragma unroll
            for (int w = 0; w < 8; w++) k += S.red[w];
            S.kee[e] = k;
        }
        __syncthreads();
    }

    // ================= EN graph: both elements =================
    stage_weights(S, wl_en, bl_en, wr_en, t);
    for (int i = t; i < (2 + NA) * FEAT; i += BLK) embeen[i] = emb_en[i];
    __syncthreads();

    for (int e = 0; e < 2; e++) {
        if (b0 + e >= nb) break;
        const float* xyz = &S.xyz[e * NE * 3];

        if (t < NPN) {
            int a = t / NE, el = t - a * NE;
            float dx = xyz[el * 3 + 0] - S.atm[a * 3 + 0];
            float dy = xyz[el * 3 + 1] - S.atm[a * 3 + 1];
            float dz = xyz[el * 3 + 2] - S.atm[a * 3 + 2];
            Sd[t] = sqrtf(dx * dx + dy * dy + dz * dz);
        }
        __syncthreads();

        #pragma unroll 2
        for (int it = t; it < NPN * 32; it += BLK) {
            int q = it >> 5, f2 = it & 31;
            float u = fminf(Sd[q] * INV_STEP, (float)(T_TAB - 2) + 0.999f);
            int idx = (int)u;
            float w = u - (float)idx;
            uint2 vv = g_tab_en[idx * 32 + f2];
            __half2 v0 = *(__half2*)&vv.x, v1 = *(__half2*)&vv.y;
            __half2 wh = __float2half2_rn(w);
            S.filt2[it] = __hfma2(wh, __hsub2(v1, v0), v0);
        }
        __syncthreads();

        // layer 0: gather (warps 0-5: 5 electrons; warps 6-15: 1 atom)
        if (warp < 6) {
            const int base = 5 * warp;
            u64 acc[5] = {0, 0, 0, 0, 0};
            #pragma unroll
            for (int aa = 0; aa < NA; aa++) {
                u64 hv = *(const u64*)&embeen[(2 + aa) * FEAT + 2 * fp];
                #pragma unroll
                for (int s = 0; s < 5; s++) {
                    float2 fv = __half22float2(S.filt2[(aa * NE + base + s) * 32 + fp]);
                    u64 f2 = pack2(fv.x, fv.y);
                    FMA2(acc[s], hv, f2, acc[s]);
                }
            }
            #pragma unroll
            for (int s = 0; s < 5; s++)
                *(u64*)&S.agg[(base + s) * FEAT + 2 * fp] = acc[s];
        } else {
            const int a = warp - 6;
            u64 su = 0, sd = 0;
            #pragma unroll
            for (int el = 0; el < NE; el++) {
                float2 fv = __half22float2(S.filt2[(a * NE + el) * 32 + fp]);
                u64 f2 = pack2(fv.x, fv.y);
                if (el < 15) { ADD2(su, su, f2); } else { ADD2(sd, sd, f2); }
            }
            u64 e0 = *(const u64*)&embeen[2 * fp];
            u64 e1 = *(const u64*)&embeen[FEAT + 2 * fp];
            u64 c, z = 0;
            FMA2(c, su, e0, z); FMA2(c, sd, e1, c);
            *(u64*)&S.agg[(NE + a) * FEAT + 2 * fp] = c;
        }
        __syncthreads();
        if (warp < 10) linear4_l0<false>(S, embeen, 4 * warp, NN, fp);
        __syncthreads();

        // layer 1: full gather + fold
        if (warp < 6) {
            const int base = 5 * warp;
            u64 acc[5] = {0, 0, 0, 0, 0};
            #pragma unroll
            for (int aa = 0; aa < NA; aa++) {
                u64 hv = *(const u64*)&S.h[(NE + aa) * FEAT + 2 * fp];
                #pragma unroll
                for (int s = 0; s < 5; s++) {
                    float2 fv = __half22float2(S.filt2[(aa * NE + base + s) * 32 + fp]);
                    u64 f2 = pack2(fv.x, fv.y);
                    FMA2(acc[s], hv, f2, acc[s]);
                }
            }
            #pragma unroll
            for (int s = 0; s < 5; s++)
                *(u64*)&S.agg[(base + s) * FEAT + 2 * fp] = acc[s];
        } else {
            const int a = warp - 6;
            u64 ca = 0, cb = 0;
            #pragma unroll
            for (int el = 0; el < NE; el++) {
                u64 hv = *(const u64*)&S.h[el * FEAT + 2 * fp];
                float2 fv = __half22float2(S.filt2[(a * NE + el) * 32 + fp]);
                u64 f2 = pack2(fv.x, fv.y);
                if (el & 1) { FMA2(cb, hv, f2, cb); } else { FMA2(ca, hv, f2, ca); }
            }
            ADD2(ca, ca, cb);
            *(u64*)&S.agg[(NE + a) * FEAT + 2 * fp] = ca;
        }
        __syncthreads();
        if (warp < 10) linear4_fold(S, S.red, warp, 4 * warp, NN, fp);
        __syncthreads();
        if (t == 0) {
            float k = br_en[0];
            #pragma unroll
            for (int w = 0; w < 10; w++) k += S.red[w];
            out[b0 + e] = expf(S.kee[e] + k);
        }
        __syncthreads();
    }
}

// ---------------------------------------------------------------------------
extern "C" void kernel_launch(void* const* d_in, const int* in_sizes, int n_in,
                              void* d_out, int out_size) {
    const float* pos    = (const float*)d_in[0];
    const float* atoms  = (const float*)d_in[1];
    const float* emb_ee = (const float*)d_in[2];
    const float* wf_ee  = (const float*)d_in[3];
    const float* bf_ee  = (const float*)d_in[4];
    const float* wl_ee  = (const float*)d_in[5];
    const float* bl_ee  = (const float*)d_in[6];
    const float* wr_ee  = (const float*)d_in[7];
    const float* br_ee  = (const float*)d_in[8];
    const float* emb_en = (const float*)d_in[9];
    const float* wf_en  = (const float*)d_in[10];
    const float* bf_en  = (const float*)d_in[11];
    const float* wl_en  = (const float*)d_in[12];
    const float* bl_en  = (const float*)d_in[13];
    const float* wr_en  = (const float*)d_in[14];
    const float* br_en  = (const float*)d_in[15];
    float* out = (float*)d_out;

    int nb = in_sizes[0] / (NE * 3);
    int nblk = (nb + 1) / 2;

    cudaFuncSetAttribute(jastrow_kernel,
                         cudaFuncAttributeMaxDynamicSharedMemorySize,
                         (int)sizeof(Smem));

    build_tab_kernel<<<dim3(T_TAB / 32, 2), 256>>>(wf_ee, bf_ee, wf_en, bf_en);
    jastrow_kernel<<<nblk, BLK, sizeof(Smem)>>>(
        pos, atoms, emb_ee, wl_ee, bl_ee, wr_ee, br_ee,
        emb_en, wl_en, bl_en, wr_en, br_en, out, nb);
}